// round 6
// baseline (speedup 1.0000x reference)
#include <cuda_runtime.h>
#include <cuda_fp16.h>
#include <math.h>
#include <stdint.h>

#define NMAX 100000
#define EMAX 2000000

// Scratch (alloc-free: __device__ globals, zero-initialized at load)
__device__ __half g_t16a[NMAX * 64];   // layer-1 linear output (fp16)
__device__ __half g_t16b[NMAX * 64];   // layer-2 linear output (fp16)
__device__ float  g_t32[NMAX * 64];    // layer-3 linear output (fp32)
__device__ int    g_deg[NMAX];         // self-cleaning (scan3 re-zeroes)
__device__ int    g_incl[NMAX];
__device__ int    g_rp[NMAX + 1];
__device__ int    g_cursor[NMAX];
__device__ int    g_bsum[128];
__device__ int    g_csr[EMAX];

__device__ __forceinline__ uint32_t f2tf32(float f) {
    uint32_t r;
    asm("cvt.rna.tf32.f32 %0, %1;" : "=r"(r) : "f"(f));
    return r;
}

// ---------------------------------------------------------------------------
// Standalone tensor-core GEMM (layer 1): t16a[n,64] = x[n,128] @ W1
// ---------------------------------------------------------------------------
template <int K>
__global__ __launch_bounds__(256)
void gemm_tc_kernel(const float* __restrict__ in, const float* __restrict__ W,
                    __half* __restrict__ out, int n) {
    constexpr int KS = K / 8;
    __shared__ uint32_t Wf[KS * 8 * 32 * 2];

    const int tid = threadIdx.x;
    for (int idx = tid; idx < K * 64; idx += 256) {
        int k  = idx >> 6;
        int nn = idx & 63;
        int ks = k >> 3, kk = k & 7;
        int ch = kk >> 2, c = kk & 3;
        int nb = nn >> 3, ng = nn & 7;
        int lane = ng * 4 + c;
        Wf[(((ks * 8 + nb) * 32) + lane) * 2 + ch] = f2tf32(W[idx]);
    }
    __syncthreads();

    const int w    = tid >> 5;
    const int lane = tid & 31;
    const int grp  = lane >> 2;
    const int tig  = lane & 3;

    const int r0 = blockIdx.x * 128 + w * 16 + grp;
    const int r1 = r0 + 8;
    const bool v0 = r0 < n;
    const bool v1 = r1 < n;
    const float* p0 = in + (long)r0 * K + tig;
    const float* p1 = in + (long)r1 * K + tig;

    float acc[8][4];
#pragma unroll
    for (int nb = 0; nb < 8; nb++)
#pragma unroll
        for (int j = 0; j < 4; j++) acc[nb][j] = 0.f;

#pragma unroll
    for (int ks = 0; ks < KS; ks++) {
        float a0f = v0 ? __ldg(p0 + ks * 8)     : 0.f;
        float a1f = v1 ? __ldg(p1 + ks * 8)     : 0.f;
        float a2f = v0 ? __ldg(p0 + ks * 8 + 4) : 0.f;
        float a3f = v1 ? __ldg(p1 + ks * 8 + 4) : 0.f;
        uint32_t a0 = f2tf32(a0f), a1 = f2tf32(a1f);
        uint32_t a2 = f2tf32(a2f), a3 = f2tf32(a3f);

        const uint32_t* wbase = &Wf[(ks * 8) * 64 + lane * 2];
#pragma unroll
        for (int nb = 0; nb < 8; nb++) {
            uint2 bb = *(const uint2*)(wbase + nb * 64);
            asm volatile(
                "mma.sync.aligned.m16n8k8.row.col.f32.tf32.tf32.f32 "
                "{%0,%1,%2,%3}, {%4,%5,%6,%7}, {%8,%9}, {%0,%1,%2,%3};"
                : "+f"(acc[nb][0]), "+f"(acc[nb][1]),
                  "+f"(acc[nb][2]), "+f"(acc[nb][3])
                : "r"(a0), "r"(a1), "r"(a2), "r"(a3),
                  "r"(bb.x), "r"(bb.y));
        }
    }

#pragma unroll
    for (int nb = 0; nb < 8; nb++) {
        int col = nb * 8 + tig * 2;
        if (v0) *(__half2*)&out[(long)r0 * 64 + col] = __floats2half2_rn(acc[nb][0], acc[nb][1]);
        if (v1) *(__half2*)&out[(long)r1 * 64 + col] = __floats2half2_rn(acc[nb][2], acc[nb][3]);
    }
}

// ---------------------------------------------------------------------------
// Fused: gather-reduce(tprev) + bias + relu  -> smem hs (fp16) -> MMA with W
// Block = 128 nodes. HALF_OUT selects half2 vs float2 epilogue.
// ---------------------------------------------------------------------------
template <bool HALF_OUT>
__global__ __launch_bounds__(256)
void fused_gather_gemm_kernel(const int* __restrict__ rp, const int* __restrict__ csr,
                              const __half* __restrict__ tprev,
                              const float* __restrict__ bias,
                              const float* __restrict__ W,
                              void* __restrict__ out_, int n) {
    constexpr int K = 64, KS = 8;
    __shared__ uint32_t Wf[KS * 8 * 32 * 2];   // 16 KB
    __shared__ __half2  hs[128][34];           // 17.4 KB, stride 34 u32 (bank-safe)

    const int tid  = threadIdx.x;
    const int w    = tid >> 5;
    const int lane = tid & 31;
    const int row0 = blockIdx.x * 128;

    // Stage W fragments
    for (int idx = tid; idx < K * 64; idx += 256) {
        int k  = idx >> 6;
        int nn = idx & 63;
        int ks = k >> 3, kk = k & 7;
        int ch = kk >> 2, c = kk & 3;
        int nb = nn >> 3, ng = nn & 7;
        int ln = ng * 4 + c;
        Wf[(((ks * 8 + nb) * 32) + ln) * 2 + ch] = f2tf32(W[idx]);
    }

    // Gather stage: each warp produces 16 node rows into hs
    const __half2* tp = (const __half2*)tprev;
    float2 bb = *(const float2*)&bias[lane * 2];
#pragma unroll 1
    for (int i = 0; i < 16; i++) {
        int node = row0 + w * 16 + i;
        float ax = 0.f, ay = 0.f;
        if (node < n) {
            int s0 = __ldg(&rp[node]);
            int s1 = __ldg(&rp[node + 1]);
            int e = s0;
            for (; e + 7 < s1; e += 8) {
                float2 v[8];
#pragma unroll
                for (int j = 0; j < 8; j++) {
                    int src = __ldg(&csr[e + j]);
                    v[j] = __half22float2(tp[(long)src * 32 + lane]);
                }
#pragma unroll
                for (int j = 0; j < 8; j++) { ax += v[j].x; ay += v[j].y; }
            }
            for (; e < s1; e++) {
                int src = __ldg(&csr[e]);
                float2 v = __half22float2(tp[(long)src * 32 + lane]);
                ax += v.x; ay += v.y;
            }
            ax = fmaxf(ax + bb.x, 0.f);
            ay = fmaxf(ay + bb.y, 0.f);
        }
        hs[w * 16 + i][lane] = __floats2half2_rn(ax, ay);
    }
    __syncthreads();

    // MMA stage: A from hs
    const int grp = lane >> 2;
    const int tig = lane & 3;
    const int lr0 = w * 16 + grp;
    const int lr1 = lr0 + 8;
    const int th  = tig >> 1;
    const int sel = tig & 1;

    float acc[8][4];
#pragma unroll
    for (int nb = 0; nb < 8; nb++)
#pragma unroll
        for (int j = 0; j < 4; j++) acc[nb][j] = 0.f;

#pragma unroll
    for (int ks = 0; ks < KS; ks++) {
        __half2 p00 = hs[lr0][ks * 4 + th];
        __half2 p10 = hs[lr1][ks * 4 + th];
        __half2 p01 = hs[lr0][ks * 4 + 2 + th];
        __half2 p11 = hs[lr1][ks * 4 + 2 + th];
        float a0f = sel ? __high2float(p00) : __low2float(p00);
        float a1f = sel ? __high2float(p10) : __low2float(p10);
        float a2f = sel ? __high2float(p01) : __low2float(p01);
        float a3f = sel ? __high2float(p11) : __low2float(p11);
        uint32_t a0 = f2tf32(a0f), a1 = f2tf32(a1f);
        uint32_t a2 = f2tf32(a2f), a3 = f2tf32(a3f);

        const uint32_t* wbase = &Wf[(ks * 8) * 64 + lane * 2];
#pragma unroll
        for (int nb = 0; nb < 8; nb++) {
            uint2 wb = *(const uint2*)(wbase + nb * 64);
            asm volatile(
                "mma.sync.aligned.m16n8k8.row.col.f32.tf32.tf32.f32 "
                "{%0,%1,%2,%3}, {%4,%5,%6,%7}, {%8,%9}, {%0,%1,%2,%3};"
                : "+f"(acc[nb][0]), "+f"(acc[nb][1]),
                  "+f"(acc[nb][2]), "+f"(acc[nb][3])
                : "r"(a0), "r"(a1), "r"(a2), "r"(a3),
                  "r"(wb.x), "r"(wb.y));
        }
    }

    const int r0 = row0 + lr0;
    const int r1 = row0 + lr1;
    const bool v0 = r0 < n;
    const bool v1 = r1 < n;
#pragma unroll
    for (int nb = 0; nb < 8; nb++) {
        int col = nb * 8 + tig * 2;
        if (HALF_OUT) {
            __half* out = (__half*)out_;
            if (v0) *(__half2*)&out[(long)r0 * 64 + col] = __floats2half2_rn(acc[nb][0], acc[nb][1]);
            if (v1) *(__half2*)&out[(long)r1 * 64 + col] = __floats2half2_rn(acc[nb][2], acc[nb][3]);
        } else {
            float* out = (float*)out_;
            if (v0) *(float2*)&out[(long)r0 * 64 + col] = make_float2(acc[nb][0], acc[nb][1]);
            if (v1) *(float2*)&out[(long)r1 * 64 + col] = make_float2(acc[nb][2], acc[nb][3]);
        }
    }
}

// ---------------------------------------------------------------------------
// CSR construction (4 kernels: hist, scan1, scan3, fill)
// ---------------------------------------------------------------------------
__global__ void hist_kernel(const int* __restrict__ ei, int E, int* __restrict__ deg) {
    int e = blockIdx.x * blockDim.x + threadIdx.x;
    if (e < E) atomicAdd(&deg[ei[E + e]], 1);
}

__global__ __launch_bounds__(256)
void scan1_kernel(const int* __restrict__ deg, int n,
                  int* __restrict__ incl, int* __restrict__ bsum) {
    __shared__ int s[1024];
    const int base = blockIdx.x * 1024;
    const int t = threadIdx.x;
#pragma unroll
    for (int j = 0; j < 4; j++) {
        int idx = t + j * 256;
        s[idx] = (base + idx < n) ? deg[base + idx] : 0;
    }
    __syncthreads();
    for (int off = 1; off < 1024; off <<= 1) {
        int v[4];
#pragma unroll
        for (int j = 0; j < 4; j++) {
            int idx = t + j * 256;
            v[j] = (idx >= off) ? s[idx - off] : 0;
        }
        __syncthreads();
#pragma unroll
        for (int j = 0; j < 4; j++) s[t + j * 256] += v[j];
        __syncthreads();
    }
#pragma unroll
    for (int j = 0; j < 4; j++) {
        int idx = t + j * 256;
        if (base + idx < n) incl[base + idx] = s[idx];
    }
    if (t == 0) bsum[blockIdx.x] = s[1023];
}

// scan3: in-block scan of bsum (<=128 entries) + exclusive row_ptr + cursor,
// then re-zero deg for the next graph replay (self-cleaning).
__global__ __launch_bounds__(256)
void scan3_kernel(const int* __restrict__ incl, int* __restrict__ deg,
                  const int* __restrict__ bsum, int nb, int n, int E,
                  int* __restrict__ rp, int* __restrict__ cursor) {
    __shared__ int s[128];
    const int t = threadIdx.x;
    if (t < 128) s[t] = (t < nb) ? bsum[t] : 0;
    __syncthreads();
    for (int off = 1; off < 128; off <<= 1) {
        int v = 0;
        if (t < 128 && t >= off) v = s[t - off];
        __syncthreads();
        if (t < 128) s[t] += v;
        __syncthreads();
    }
    int i = blockIdx.x * blockDim.x + t;
    if (i >= n) return;
    int b = i >> 10;
    int add = b ? s[b - 1] : 0;
    int excl = incl[i] - deg[i] + add;
    rp[i] = excl;
    cursor[i] = excl;
    deg[i] = 0;                    // self-clean for next replay
    if (i == n - 1) rp[n] = E;
}

__global__ void fill_kernel(const int* __restrict__ ei, int E,
                            int* __restrict__ cursor, int* __restrict__ csr) {
    int e = blockIdx.x * blockDim.x + threadIdx.x;
    if (e >= E) return;
    int src = ei[e];
    int dst = ei[E + e];
    int pos = atomicAdd(&cursor[dst], 1);
    csr[pos] = src;
}

// ---------------------------------------------------------------------------
// Final gather (fp32 t) + bias + sigmoid
// ---------------------------------------------------------------------------
__global__ __launch_bounds__(256)
void gather_f32_sig_kernel(const int* __restrict__ rp, const int* __restrict__ csr,
                           const float* __restrict__ t, const float* __restrict__ bias,
                           float* __restrict__ out, int n) {
    int warp = (blockIdx.x * blockDim.x + threadIdx.x) >> 5;
    int lane = threadIdx.x & 31;
    if (warp >= n) return;

    int s0 = rp[warp];
    int s1 = rp[warp + 1];

    float ax = 0.f, ay = 0.f;
    int e = s0;
    for (; e + 3 < s1; e += 4) {
        int src0 = __ldg(&csr[e + 0]);
        int src1 = __ldg(&csr[e + 1]);
        int src2 = __ldg(&csr[e + 2]);
        int src3 = __ldg(&csr[e + 3]);
        float2 v0 = *(const float2*)&t[(long)src0 * 64 + lane * 2];
        float2 v1 = *(const float2*)&t[(long)src1 * 64 + lane * 2];
        float2 v2 = *(const float2*)&t[(long)src2 * 64 + lane * 2];
        float2 v3 = *(const float2*)&t[(long)src3 * 64 + lane * 2];
        ax += (v0.x + v1.x) + (v2.x + v3.x);
        ay += (v0.y + v1.y) + (v2.y + v3.y);
    }
    for (; e < s1; e++) {
        int src = __ldg(&csr[e]);
        float2 v = *(const float2*)&t[(long)src * 64 + lane * 2];
        ax += v.x; ay += v.y;
    }

    float2 bb = *(const float2*)&bias[lane * 2];
    ax += bb.x; ay += bb.y;
    float2 r;
    r.x = 1.f / (1.f + __expf(-ax));
    r.y = 1.f / (1.f + __expf(-ay));
    *(float2*)&out[(long)warp * 64 + lane * 2] = r;
}

extern "C" void kernel_launch(void* const* d_in, const int* in_sizes, int n_in,
                              void* d_out, int out_size) {
    const float* x  = (const float*)d_in[0];
    const int*   ei = (const int*)d_in[1];
    const float* W1 = (const float*)d_in[2];
    const float* b1 = (const float*)d_in[3];
    const float* W2 = (const float*)d_in[4];
    const float* b2 = (const float*)d_in[5];
    const float* W3 = (const float*)d_in[6];
    const float* b3 = (const float*)d_in[7];
    float* out = (float*)d_out;

    const int N = in_sizes[0] / 128;
    const int E = in_sizes[1] / 2;

    __half *t16a, *t16b;
    float* t32;
    int *deg, *incl, *rp, *cursor, *bsum, *csr;
    cudaGetSymbolAddress((void**)&t16a,   g_t16a);
    cudaGetSymbolAddress((void**)&t16b,   g_t16b);
    cudaGetSymbolAddress((void**)&t32,    g_t32);
    cudaGetSymbolAddress((void**)&deg,    g_deg);
    cudaGetSymbolAddress((void**)&incl,   g_incl);
    cudaGetSymbolAddress((void**)&rp,     g_rp);
    cudaGetSymbolAddress((void**)&cursor, g_cursor);
    cudaGetSymbolAddress((void**)&bsum,   g_bsum);
    cudaGetSymbolAddress((void**)&csr,    g_csr);

    const int nb_scan = (N + 1023) / 1024;
    const int nblk = (N + 255) / 256;
    const int eblk = (E + 255) / 256;
    const int gb   = (N + 127) / 128;
    const int wb   = (N + 7) / 8;

    // CSR build + layer-1 GEMM interleaved (gemm1 at slot 4 for ncu profiling)
    hist_kernel<<<eblk, 256>>>(ei, E, deg);                              // 1
    scan1_kernel<<<nb_scan, 256>>>(deg, N, incl, bsum);                  // 2
    scan3_kernel<<<nblk, 256>>>(incl, deg, bsum, nb_scan, N, E, rp, cursor); // 3
    gemm_tc_kernel<128><<<gb, 256>>>(x, W1, t16a, N);                    // 4 (profiled)
    fill_kernel<<<eblk, 256>>>(ei, E, cursor, csr);                      // 5

    // Layer 1 aggregate + layer 2 linear (fused)
    fused_gather_gemm_kernel<true><<<gb, 256>>>(rp, csr, t16a, b1, W2, t16b, N);   // 6
    // Layer 2 aggregate + layer 3 linear (fused)
    fused_gather_gemm_kernel<false><<<gb, 256>>>(rp, csr, t16b, b2, W3, t32, N);   // 7
    // Layer 3 aggregate + sigmoid
    gather_f32_sig_kernel<<<wb, 256>>>(rp, csr, t32, b3, out, N);        // 8
}

// round 8
// speedup vs baseline: 1.1760x; 1.1760x over previous
#include <cuda_runtime.h>
#include <cuda_fp16.h>
#include <math.h>
#include <stdint.h>

#define NMAX 100000
#define EMAX 2000000

// Scratch (alloc-free: __device__ globals, zero-initialized at load)
__device__ __half g_t16a[NMAX * 64];   // layer-1 linear output (fp16)
__device__ __half g_t16b[NMAX * 64];   // layer-2 linear output (fp16)
__device__ float  g_t32[NMAX * 64];    // layer-3 linear output (fp32)
__device__ float  g_h[NMAX * 64];      // activations (fp32)
__device__ int    g_deg[NMAX];         // self-cleaning (scan3 re-zeroes)
__device__ int    g_incl[NMAX];
__device__ int    g_rp[NMAX + 1];
__device__ int    g_cursor[NMAX];
__device__ int    g_bsum[128];
__device__ int    g_csr[EMAX];
// Fragment-layout weights: W1 (16 ks) + W2 (8 ks) + W3 (8 ks), uint2 each
__device__ uint2  g_wf[4096 + 2048 + 2048];

__device__ __forceinline__ uint32_t f2tf32(float f) {
    uint32_t r;
    asm("cvt.rna.tf32.f32 %0, %1;" : "=r"(r) : "f"(f));
    return r;
}

// ---------------------------------------------------------------------------
// W fragment prep: one block per weight matrix.
// wf[(ks*8 + nb)*32 + lane] = {tf32 W[ks*8 + (lane&3)][nb*8 + (lane>>2)],
//                              tf32 W[ks*8 + (lane&3) + 4][same col]}
// ---------------------------------------------------------------------------
__global__ __launch_bounds__(256)
void wprep2_kernel(const float* __restrict__ W1, const float* __restrict__ W2,
                   const float* __restrict__ W3, uint32_t* __restrict__ wf) {
    const float* W = (blockIdx.x == 0) ? W1 : (blockIdx.x == 1) ? W2 : W3;
    const int K = (blockIdx.x == 0) ? 128 : 64;
    uint32_t* dst = wf + ((blockIdx.x == 0) ? 0 : (blockIdx.x == 1) ? 8192 : 12288);
    for (int idx = threadIdx.x; idx < K * 64; idx += 256) {
        int k  = idx >> 6;
        int nn = idx & 63;
        int ks = k >> 3, kk = k & 7;
        int ch = kk >> 2, c = kk & 3;
        int nb = nn >> 3, ng = nn & 7;
        int lane = ng * 4 + c;
        dst[(((ks * 8 + nb) * 32) + lane) * 2 + ch] = f2tf32(W[idx]);
    }
}

// ---------------------------------------------------------------------------
// Tensor-core GEMM with smem A staging: out[n,64] = in[n,K] @ W  (Wf in gmem)
// 256 threads / 8 warps, 128 rows per block, K-chunks of 32.
// smem pad 36 floats/row -> fragment LDS is bank-conflict-free.
// ---------------------------------------------------------------------------
template <int K, bool HALF_OUT>
__global__ __launch_bounds__(256)
void gemm_tc_kernel(const float* __restrict__ in, const uint2* __restrict__ wf,
                    void* __restrict__ out_, int n) {
    constexpr int NCHUNK = K / 32;
    __shared__ float hT[128][36];   // 18.4 KB

    const int tid  = threadIdx.x;
    const int w    = tid >> 5;
    const int lane = tid & 31;
    const int grp  = lane >> 2;
    const int tig  = lane & 3;
    const int row0 = blockIdx.x * 128;

    const int lr0 = w * 16 + grp;
    const int lr1 = lr0 + 8;

    float acc[8][4];
#pragma unroll
    for (int nb = 0; nb < 8; nb++)
#pragma unroll
        for (int j = 0; j < 4; j++) acc[nb][j] = 0.f;

#pragma unroll 1
    for (int c = 0; c < NCHUNK; c++) {
        // Stage A chunk: 128 rows x 32 k, coalesced float4 loads.
#pragma unroll
        for (int it = 0; it < 4; it++) {
            int idx = tid + it * 256;
            int r  = idx >> 3;
            int q  = idx & 7;
            int grow = row0 + r;
            float4 v = make_float4(0.f, 0.f, 0.f, 0.f);
            if (grow < n) v = *(const float4*)&in[(long)grow * K + c * 32 + q * 4];
            hT[r][q * 4 + 0] = v.x;
            hT[r][q * 4 + 1] = v.y;
            hT[r][q * 4 + 2] = v.z;
            hT[r][q * 4 + 3] = v.w;
        }
        __syncthreads();

#pragma unroll
        for (int ks = 0; ks < 4; ks++) {
            uint32_t a0 = f2tf32(hT[lr0][ks * 8 + tig]);
            uint32_t a1 = f2tf32(hT[lr1][ks * 8 + tig]);
            uint32_t a2 = f2tf32(hT[lr0][ks * 8 + tig + 4]);
            uint32_t a3 = f2tf32(hT[lr1][ks * 8 + tig + 4]);

            const uint2* wbase = wf + ((c * 4 + ks) * 8) * 32 + lane;
#pragma unroll
            for (int nb = 0; nb < 8; nb++) {
                uint2 bb = __ldg(wbase + nb * 32);
                asm volatile(
                    "mma.sync.aligned.m16n8k8.row.col.f32.tf32.tf32.f32 "
                    "{%0,%1,%2,%3}, {%4,%5,%6,%7}, {%8,%9}, {%0,%1,%2,%3};"
                    : "+f"(acc[nb][0]), "+f"(acc[nb][1]),
                      "+f"(acc[nb][2]), "+f"(acc[nb][3])
                    : "r"(a0), "r"(a1), "r"(a2), "r"(a3),
                      "r"(bb.x), "r"(bb.y));
            }
        }
        __syncthreads();
    }

    const int r0 = row0 + lr0;
    const int r1 = row0 + lr1;
    const bool v0 = r0 < n;
    const bool v1 = r1 < n;
#pragma unroll
    for (int nb = 0; nb < 8; nb++) {
        int col = nb * 8 + tig * 2;
        if (HALF_OUT) {
            __half* out = (__half*)out_;
            if (v0) *(__half2*)&out[(long)r0 * 64 + col] = __floats2half2_rn(acc[nb][0], acc[nb][1]);
            if (v1) *(__half2*)&out[(long)r1 * 64 + col] = __floats2half2_rn(acc[nb][2], acc[nb][3]);
        } else {
            float* out = (float*)out_;
            if (v0) *(float2*)&out[(long)r0 * 64 + col] = make_float2(acc[nb][0], acc[nb][1]);
            if (v1) *(float2*)&out[(long)r1 * 64 + col] = make_float2(acc[nb][2], acc[nb][3]);
        }
    }
}

// ---------------------------------------------------------------------------
// CSR construction (4 kernels)
// ---------------------------------------------------------------------------
__global__ void hist_kernel(const int* __restrict__ ei, int E, int* __restrict__ deg) {
    int e = blockIdx.x * blockDim.x + threadIdx.x;
    if (e < E) atomicAdd(&deg[ei[E + e]], 1);
}

__global__ __launch_bounds__(256)
void scan1_kernel(const int* __restrict__ deg, int n,
                  int* __restrict__ incl, int* __restrict__ bsum) {
    __shared__ int s[1024];
    const int base = blockIdx.x * 1024;
    const int t = threadIdx.x;
#pragma unroll
    for (int j = 0; j < 4; j++) {
        int idx = t + j * 256;
        s[idx] = (base + idx < n) ? deg[base + idx] : 0;
    }
    __syncthreads();
    for (int off = 1; off < 1024; off <<= 1) {
        int v[4];
#pragma unroll
        for (int j = 0; j < 4; j++) {
            int idx = t + j * 256;
            v[j] = (idx >= off) ? s[idx - off] : 0;
        }
        __syncthreads();
#pragma unroll
        for (int j = 0; j < 4; j++) s[t + j * 256] += v[j];
        __syncthreads();
    }
#pragma unroll
    for (int j = 0; j < 4; j++) {
        int idx = t + j * 256;
        if (base + idx < n) incl[base + idx] = s[idx];
    }
    if (t == 0) bsum[blockIdx.x] = s[1023];
}

__global__ __launch_bounds__(256)
void scan3_kernel(const int* __restrict__ incl, int* __restrict__ deg,
                  const int* __restrict__ bsum, int nb, int n, int E,
                  int* __restrict__ rp, int* __restrict__ cursor) {
    __shared__ int s[128];
    const int t = threadIdx.x;
    if (t < 128) s[t] = (t < nb) ? bsum[t] : 0;
    __syncthreads();
    for (int off = 1; off < 128; off <<= 1) {
        int v = 0;
        if (t < 128 && t >= off) v = s[t - off];
        __syncthreads();
        if (t < 128) s[t] += v;
        __syncthreads();
    }
    int i = blockIdx.x * blockDim.x + t;
    if (i >= n) return;
    int b = i >> 10;
    int add = b ? s[b - 1] : 0;
    int excl = incl[i] - deg[i] + add;
    rp[i] = excl;
    cursor[i] = excl;
    deg[i] = 0;
    if (i == n - 1) rp[n] = E;
}

__global__ void fill_kernel(const int* __restrict__ ei, int E,
                            int* __restrict__ cursor, int* __restrict__ csr) {
    int e = blockIdx.x * blockDim.x + threadIdx.x;
    if (e >= E) return;
    int src = ei[e];
    int dst = ei[E + e];
    int pos = atomicAdd(&cursor[dst], 1);
    csr[pos] = src;
}

// ---------------------------------------------------------------------------
// Gather-reduce (fp16 t) + bias + relu -> fp32 h
// ---------------------------------------------------------------------------
__global__ __launch_bounds__(256)
void gather_h2_kernel(const int* __restrict__ rp, const int* __restrict__ csr,
                      const __half* __restrict__ t, const float* __restrict__ bias,
                      float* __restrict__ out, int n) {
    int warp = (blockIdx.x * blockDim.x + threadIdx.x) >> 5;
    int lane = threadIdx.x & 31;
    if (warp >= n) return;

    int s0 = rp[warp];
    int s1 = rp[warp + 1];
    const __half2* tp = (const __half2*)t;

    float ax = 0.f, ay = 0.f;
    int e = s0;
    for (; e + 7 < s1; e += 8) {
        float2 v[8];
#pragma unroll
        for (int j = 0; j < 8; j++) {
            int src = __ldg(&csr[e + j]);
            v[j] = __half22float2(tp[(long)src * 32 + lane]);
        }
#pragma unroll
        for (int j = 0; j < 8; j++) { ax += v[j].x; ay += v[j].y; }
    }
    for (; e < s1; e++) {
        int src = __ldg(&csr[e]);
        float2 v = __half22float2(tp[(long)src * 32 + lane]);
        ax += v.x; ay += v.y;
    }

    float2 bb = *(const float2*)&bias[lane * 2];
    float2 r;
    r.x = fmaxf(ax + bb.x, 0.f);
    r.y = fmaxf(ay + bb.y, 0.f);
    *(float2*)&out[(long)warp * 64 + lane * 2] = r;
}

// ---------------------------------------------------------------------------
// Final gather (fp32 t) + bias + sigmoid
// ---------------------------------------------------------------------------
__global__ __launch_bounds__(256)
void gather_f32_sig_kernel(const int* __restrict__ rp, const int* __restrict__ csr,
                           const float* __restrict__ t, const float* __restrict__ bias,
                           float* __restrict__ out, int n) {
    int warp = (blockIdx.x * blockDim.x + threadIdx.x) >> 5;
    int lane = threadIdx.x & 31;
    if (warp >= n) return;

    int s0 = rp[warp];
    int s1 = rp[warp + 1];

    float ax = 0.f, ay = 0.f;
    int e = s0;
    for (; e + 3 < s1; e += 4) {
        int src0 = __ldg(&csr[e + 0]);
        int src1 = __ldg(&csr[e + 1]);
        int src2 = __ldg(&csr[e + 2]);
        int src3 = __ldg(&csr[e + 3]);
        float2 v0 = *(const float2*)&t[(long)src0 * 64 + lane * 2];
        float2 v1 = *(const float2*)&t[(long)src1 * 64 + lane * 2];
        float2 v2 = *(const float2*)&t[(long)src2 * 64 + lane * 2];
        float2 v3 = *(const float2*)&t[(long)src3 * 64 + lane * 2];
        ax += (v0.x + v1.x) + (v2.x + v3.x);
        ay += (v0.y + v1.y) + (v2.y + v3.y);
    }
    for (; e < s1; e++) {
        int src = __ldg(&csr[e]);
        float2 v = *(const float2*)&t[(long)src * 64 + lane * 2];
        ax += v.x; ay += v.y;
    }

    float2 bb = *(const float2*)&bias[lane * 2];
    ax += bb.x; ay += bb.y;
    float2 r;
    r.x = 1.f / (1.f + __expf(-ax));
    r.y = 1.f / (1.f + __expf(-ay));
    *(float2*)&out[(long)warp * 64 + lane * 2] = r;
}

extern "C" void kernel_launch(void* const* d_in, const int* in_sizes, int n_in,
                              void* d_out, int out_size) {
    const float* x  = (const float*)d_in[0];
    const int*   ei = (const int*)d_in[1];
    const float* W1 = (const float*)d_in[2];
    const float* b1 = (const float*)d_in[3];
    const float* W2 = (const float*)d_in[4];
    const float* b2 = (const float*)d_in[5];
    const float* W3 = (const float*)d_in[6];
    const float* b3 = (const float*)d_in[7];
    float* out = (float*)d_out;

    const int N = in_sizes[0] / 128;
    const int E = in_sizes[1] / 2;

    __half *t16a, *t16b;
    float *t32, *h;
    int *deg, *incl, *rp, *cursor, *bsum, *csr;
    uint2* wf;
    cudaGetSymbolAddress((void**)&t16a,   g_t16a);
    cudaGetSymbolAddress((void**)&t16b,   g_t16b);
    cudaGetSymbolAddress((void**)&t32,    g_t32);
    cudaGetSymbolAddress((void**)&h,      g_h);
    cudaGetSymbolAddress((void**)&deg,    g_deg);
    cudaGetSymbolAddress((void**)&incl,   g_incl);
    cudaGetSymbolAddress((void**)&rp,     g_rp);
    cudaGetSymbolAddress((void**)&cursor, g_cursor);
    cudaGetSymbolAddress((void**)&bsum,   g_bsum);
    cudaGetSymbolAddress((void**)&csr,    g_csr);
    cudaGetSymbolAddress((void**)&wf,     g_wf);

    const int nb_scan = (N + 1023) / 1024;
    const int nblk = (N + 255) / 256;
    const int eblk = (E + 255) / 256;
    const int gb   = (N + 127) / 128;
    const int wb   = (N + 7) / 8;

    hist_kernel<<<eblk, 256>>>(ei, E, deg);                                  // 1
    wprep2_kernel<<<3, 256>>>(W1, W2, W3, (uint32_t*)wf);                    // 2
    scan1_kernel<<<nb_scan, 256>>>(deg, N, incl, bsum);                      // 3
    gemm_tc_kernel<128, true><<<gb, 256>>>(x, wf, t16a, N);                  // 4 (profiled)
    scan3_kernel<<<nblk, 256>>>(incl, deg, bsum, nb_scan, N, E, rp, cursor); // 5
    fill_kernel<<<eblk, 256>>>(ei, E, cursor, csr);                          // 6

    gather_h2_kernel<<<wb, 256>>>(rp, csr, t16a, b1, h, N);                  // 7
    gemm_tc_kernel<64, true><<<gb, 256>>>(h, wf + 4096, t16b, N);            // 8
    gather_h2_kernel<<<wb, 256>>>(rp, csr, t16b, b2, h, N);                  // 9
    gemm_tc_kernel<64, false><<<gb, 256>>>(h, wf + 6144, t32, N);            // 10
    gather_f32_sig_kernel<<<wb, 256>>>(rp, csr, t32, b3, out, N);            // 11
}

// round 9
// speedup vs baseline: 1.2938x; 1.1002x over previous
#include <cuda_runtime.h>
#include <cuda_fp16.h>
#include <math.h>
#include <stdint.h>

#define NMAX 100000
#define EMAX 2000000

// Scratch (alloc-free: __device__ globals, zero-initialized at load)
__device__ __half g_t16a[NMAX * 64];   // layer-1 linear output (fp16)
__device__ __half g_t16b[NMAX * 64];   // layer-2 linear output (fp16)
__device__ float  g_t32[NMAX * 64];    // layer-3 linear output (fp32)
__device__ float  g_h[NMAX * 64];      // activations (fp32)
__device__ int    g_deg[NMAX];         // self-cleaning (scan3 re-zeroes)
__device__ int    g_incl[NMAX];
__device__ int    g_rp[NMAX + 1];
__device__ int    g_cursor[NMAX];
__device__ int    g_bsum[128];
__device__ int    g_csr[EMAX];
// Fragment-layout weights: W1 (16 ks) + W2 (8 ks) + W3 (8 ks), uint2 each
__device__ uint2  g_wf[4096 + 2048 + 2048];

__device__ __forceinline__ uint32_t f2tf32(float f) {
    uint32_t r;
    asm("cvt.rna.tf32.f32 %0, %1;" : "=r"(r) : "f"(f));
    return r;
}

__device__ __forceinline__ void cp_async16(uint32_t saddr, const void* gptr, bool valid) {
    int sz = valid ? 16 : 0;
    asm volatile("cp.async.cg.shared.global [%0], [%1], 16, %2;"
                 :: "r"(saddr), "l"(gptr), "r"(sz));
}

// ---------------------------------------------------------------------------
// W fragment prep: one block per weight matrix.
// ---------------------------------------------------------------------------
__global__ __launch_bounds__(256)
void wprep2_kernel(const float* __restrict__ W1, const float* __restrict__ W2,
                   const float* __restrict__ W3, uint32_t* __restrict__ wf) {
    const float* W = (blockIdx.x == 0) ? W1 : (blockIdx.x == 1) ? W2 : W3;
    const int K = (blockIdx.x == 0) ? 128 : 64;
    uint32_t* dst = wf + ((blockIdx.x == 0) ? 0 : (blockIdx.x == 1) ? 8192 : 12288);
    for (int idx = threadIdx.x; idx < K * 64; idx += 256) {
        int k  = idx >> 6;
        int nn = idx & 63;
        int ks = k >> 3, kk = k & 7;
        int ch = kk >> 2, c = kk & 3;
        int nb = nn >> 3, ng = nn & 7;
        int lane = ng * 4 + c;
        dst[(((ks * 8 + nb) * 32) + lane) * 2 + ch] = f2tf32(W[idx]);
    }
}

// ---------------------------------------------------------------------------
// Tensor-core GEMM, cp.async double-buffered A staging.
// 256 threads / 8 warps, 128 rows/block, K-chunks of 32, one barrier/chunk.
// ---------------------------------------------------------------------------
template <int K, bool HALF_OUT>
__global__ __launch_bounds__(256)
void gemm_tc_kernel(const float* __restrict__ in, const uint2* __restrict__ wf,
                    void* __restrict__ out_, int n) {
    constexpr int NCHUNK = K / 32;
    __shared__ float hT[2][128][36];   // 36.9 KB, pad 36 -> conflict-free frags

    const int tid  = threadIdx.x;
    const int w    = tid >> 5;
    const int lane = tid & 31;
    const int grp  = lane >> 2;
    const int tig  = lane & 3;
    const int row0 = blockIdx.x * 128;

    const int lr0 = w * 16 + grp;
    const int lr1 = lr0 + 8;

    // Per-thread staging coords: 1024 float4 slots, 4 per thread
    const int sr = tid >> 3;        // row  (tid*4.. pattern below)
    const int sq = tid & 7;         // quad within row

    float acc[8][4];
#pragma unroll
    for (int nb = 0; nb < 8; nb++)
#pragma unroll
        for (int j = 0; j < 4; j++) acc[nb][j] = 0.f;

    // Stage chunk c into buffer buf
    auto stage = [&](int c, int buf) {
#pragma unroll
        for (int it = 0; it < 4; it++) {
            int idx = tid + it * 256;
            int r = idx >> 3;
            int q = idx & 7;
            int grow = row0 + r;
            uint32_t sa = (uint32_t)__cvta_generic_to_shared(&hT[buf][r][q * 4]);
            cp_async16(sa, &in[(long)grow * K + c * 32 + q * 4], grow < n);
        }
        asm volatile("cp.async.commit_group;");
    };

    stage(0, 0);

#pragma unroll
    for (int c = 0; c < NCHUNK; c++) {
        asm volatile("cp.async.wait_group 0;");
        __syncthreads();                       // chunk c visible; MMA(c-1) done
        if (c + 1 < NCHUNK) stage(c + 1, (c + 1) & 1);

        const int buf = c & 1;
#pragma unroll
        for (int ks = 0; ks < 4; ks++) {
            uint32_t a0 = f2tf32(hT[buf][lr0][ks * 8 + tig]);
            uint32_t a1 = f2tf32(hT[buf][lr1][ks * 8 + tig]);
            uint32_t a2 = f2tf32(hT[buf][lr0][ks * 8 + tig + 4]);
            uint32_t a3 = f2tf32(hT[buf][lr1][ks * 8 + tig + 4]);

            const uint2* wbase = wf + ((c * 4 + ks) * 8) * 32 + lane;
#pragma unroll
            for (int nb = 0; nb < 8; nb++) {
                uint2 bb = __ldg(wbase + nb * 32);
                asm volatile(
                    "mma.sync.aligned.m16n8k8.row.col.f32.tf32.tf32.f32 "
                    "{%0,%1,%2,%3}, {%4,%5,%6,%7}, {%8,%9}, {%0,%1,%2,%3};"
                    : "+f"(acc[nb][0]), "+f"(acc[nb][1]),
                      "+f"(acc[nb][2]), "+f"(acc[nb][3])
                    : "r"(a0), "r"(a1), "r"(a2), "r"(a3),
                      "r"(bb.x), "r"(bb.y));
            }
        }
    }

    const int r0 = row0 + lr0;
    const int r1 = row0 + lr1;
    const bool v0 = r0 < n;
    const bool v1 = r1 < n;
#pragma unroll
    for (int nb = 0; nb < 8; nb++) {
        int col = nb * 8 + tig * 2;
        if (HALF_OUT) {
            __half* out = (__half*)out_;
            if (v0) *(__half2*)&out[(long)r0 * 64 + col] = __floats2half2_rn(acc[nb][0], acc[nb][1]);
            if (v1) *(__half2*)&out[(long)r1 * 64 + col] = __floats2half2_rn(acc[nb][2], acc[nb][3]);
        } else {
            float* out = (float*)out_;
            if (v0) *(float2*)&out[(long)r0 * 64 + col] = make_float2(acc[nb][0], acc[nb][1]);
            if (v1) *(float2*)&out[(long)r1 * 64 + col] = make_float2(acc[nb][2], acc[nb][3]);
        }
    }
    (void)sr; (void)sq;
}

// ---------------------------------------------------------------------------
// CSR construction (4 kernels)
// ---------------------------------------------------------------------------
__global__ void hist_kernel(const int* __restrict__ ei, int E, int* __restrict__ deg) {
    int e = blockIdx.x * blockDim.x + threadIdx.x;
    if (e < E) atomicAdd(&deg[ei[E + e]], 1);
}

__global__ __launch_bounds__(256)
void scan1_kernel(const int* __restrict__ deg, int n,
                  int* __restrict__ incl, int* __restrict__ bsum) {
    __shared__ int s[1024];
    const int base = blockIdx.x * 1024;
    const int t = threadIdx.x;
#pragma unroll
    for (int j = 0; j < 4; j++) {
        int idx = t + j * 256;
        s[idx] = (base + idx < n) ? deg[base + idx] : 0;
    }
    __syncthreads();
    for (int off = 1; off < 1024; off <<= 1) {
        int v[4];
#pragma unroll
        for (int j = 0; j < 4; j++) {
            int idx = t + j * 256;
            v[j] = (idx >= off) ? s[idx - off] : 0;
        }
        __syncthreads();
#pragma unroll
        for (int j = 0; j < 4; j++) s[t + j * 256] += v[j];
        __syncthreads();
    }
#pragma unroll
    for (int j = 0; j < 4; j++) {
        int idx = t + j * 256;
        if (base + idx < n) incl[base + idx] = s[idx];
    }
    if (t == 0) bsum[blockIdx.x] = s[1023];
}

__global__ __launch_bounds__(256)
void scan3_kernel(const int* __restrict__ incl, int* __restrict__ deg,
                  const int* __restrict__ bsum, int nb, int n, int E,
                  int* __restrict__ rp, int* __restrict__ cursor) {
    __shared__ int s[128];
    const int t = threadIdx.x;
    if (t < 128) s[t] = (t < nb) ? bsum[t] : 0;
    __syncthreads();
    for (int off = 1; off < 128; off <<= 1) {
        int v = 0;
        if (t < 128 && t >= off) v = s[t - off];
        __syncthreads();
        if (t < 128) s[t] += v;
        __syncthreads();
    }
    int i = blockIdx.x * blockDim.x + t;
    if (i >= n) return;
    int b = i >> 10;
    int add = b ? s[b - 1] : 0;
    int excl = incl[i] - deg[i] + add;
    rp[i] = excl;
    cursor[i] = excl;
    deg[i] = 0;
    if (i == n - 1) rp[n] = E;
}

__global__ void fill_kernel(const int* __restrict__ ei, int E,
                            int* __restrict__ cursor, int* __restrict__ csr) {
    int e = blockIdx.x * blockDim.x + threadIdx.x;
    if (e >= E) return;
    int src = ei[e];
    int dst = ei[E + e];
    int pos = atomicAdd(&cursor[dst], 1);
    csr[pos] = src;
}

// ---------------------------------------------------------------------------
// Gather-reduce (fp16 t) + bias + relu -> fp32 h
// ---------------------------------------------------------------------------
__global__ __launch_bounds__(256)
void gather_h2_kernel(const int* __restrict__ rp, const int* __restrict__ csr,
                      const __half* __restrict__ t, const float* __restrict__ bias,
                      float* __restrict__ out, int n) {
    int warp = (blockIdx.x * blockDim.x + threadIdx.x) >> 5;
    int lane = threadIdx.x & 31;
    if (warp >= n) return;

    int s0 = rp[warp];
    int s1 = rp[warp + 1];
    const __half2* tp = (const __half2*)t;

    float ax = 0.f, ay = 0.f;
    int e = s0;
    for (; e + 7 < s1; e += 8) {
        float2 v[8];
#pragma unroll
        for (int j = 0; j < 8; j++) {
            int src = __ldg(&csr[e + j]);
            v[j] = __half22float2(tp[(long)src * 32 + lane]);
        }
#pragma unroll
        for (int j = 0; j < 8; j++) { ax += v[j].x; ay += v[j].y; }
    }
    for (; e < s1; e++) {
        int src = __ldg(&csr[e]);
        float2 v = __half22float2(tp[(long)src * 32 + lane]);
        ax += v.x; ay += v.y;
    }

    float2 bb = *(const float2*)&bias[lane * 2];
    float2 r;
    r.x = fmaxf(ax + bb.x, 0.f);
    r.y = fmaxf(ay + bb.y, 0.f);
    *(float2*)&out[(long)warp * 64 + lane * 2] = r;
}

// ---------------------------------------------------------------------------
// Final gather (fp32 t) + bias + sigmoid
// ---------------------------------------------------------------------------
__global__ __launch_bounds__(256)
void gather_f32_sig_kernel(const int* __restrict__ rp, const int* __restrict__ csr,
                           const float* __restrict__ t, const float* __restrict__ bias,
                           float* __restrict__ out, int n) {
    int warp = (blockIdx.x * blockDim.x + threadIdx.x) >> 5;
    int lane = threadIdx.x & 31;
    if (warp >= n) return;

    int s0 = rp[warp];
    int s1 = rp[warp + 1];

    float ax = 0.f, ay = 0.f;
    int e = s0;
    for (; e + 3 < s1; e += 4) {
        int src0 = __ldg(&csr[e + 0]);
        int src1 = __ldg(&csr[e + 1]);
        int src2 = __ldg(&csr[e + 2]);
        int src3 = __ldg(&csr[e + 3]);
        float2 v0 = *(const float2*)&t[(long)src0 * 64 + lane * 2];
        float2 v1 = *(const float2*)&t[(long)src1 * 64 + lane * 2];
        float2 v2 = *(const float2*)&t[(long)src2 * 64 + lane * 2];
        float2 v3 = *(const float2*)&t[(long)src3 * 64 + lane * 2];
        ax += (v0.x + v1.x) + (v2.x + v3.x);
        ay += (v0.y + v1.y) + (v2.y + v3.y);
    }
    for (; e < s1; e++) {
        int src = __ldg(&csr[e]);
        float2 v = *(const float2*)&t[(long)src * 64 + lane * 2];
        ax += v.x; ay += v.y;
    }

    float2 bb = *(const float2*)&bias[lane * 2];
    ax += bb.x; ay += bb.y;
    float2 r;
    r.x = 1.f / (1.f + __expf(-ax));
    r.y = 1.f / (1.f + __expf(-ay));
    *(float2*)&out[(long)warp * 64 + lane * 2] = r;
}

extern "C" void kernel_launch(void* const* d_in, const int* in_sizes, int n_in,
                              void* d_out, int out_size) {
    const float* x  = (const float*)d_in[0];
    const int*   ei = (const int*)d_in[1];
    const float* W1 = (const float*)d_in[2];
    const float* b1 = (const float*)d_in[3];
    const float* W2 = (const float*)d_in[4];
    const float* b2 = (const float*)d_in[5];
    const float* W3 = (const float*)d_in[6];
    const float* b3 = (const float*)d_in[7];
    float* out = (float*)d_out;

    const int N = in_sizes[0] / 128;
    const int E = in_sizes[1] / 2;

    __half *t16a, *t16b;
    float *t32, *h;
    int *deg, *incl, *rp, *cursor, *bsum, *csr;
    uint2* wf;
    cudaGetSymbolAddress((void**)&t16a,   g_t16a);
    cudaGetSymbolAddress((void**)&t16b,   g_t16b);
    cudaGetSymbolAddress((void**)&t32,    g_t32);
    cudaGetSymbolAddress((void**)&h,      g_h);
    cudaGetSymbolAddress((void**)&deg,    g_deg);
    cudaGetSymbolAddress((void**)&incl,   g_incl);
    cudaGetSymbolAddress((void**)&rp,     g_rp);
    cudaGetSymbolAddress((void**)&cursor, g_cursor);
    cudaGetSymbolAddress((void**)&bsum,   g_bsum);
    cudaGetSymbolAddress((void**)&csr,    g_csr);
    cudaGetSymbolAddress((void**)&wf,     g_wf);

    const int nb_scan = (N + 1023) / 1024;
    const int nblk = (N + 255) / 256;
    const int eblk = (E + 255) / 256;
    const int gb   = (N + 127) / 128;
    const int wb   = (N + 7) / 8;

    hist_kernel<<<eblk, 256>>>(ei, E, deg);                                  // 1
    wprep2_kernel<<<3, 256>>>(W1, W2, W3, (uint32_t*)wf);                    // 2
    scan1_kernel<<<nb_scan, 256>>>(deg, N, incl, bsum);                      // 3
    gemm_tc_kernel<128, true><<<gb, 256>>>(x, wf, t16a, N);                  // 4 (profiled)
    scan3_kernel<<<nblk, 256>>>(incl, deg, bsum, nb_scan, N, E, rp, cursor); // 5
    fill_kernel<<<eblk, 256>>>(ei, E, cursor, csr);                          // 6

    gather_h2_kernel<<<wb, 256>>>(rp, csr, t16a, b1, h, N);                  // 7
    gemm_tc_kernel<64, true><<<gb, 256>>>(h, wf + 4096, t16b, N);            // 8
    gather_h2_kernel<<<wb, 256>>>(rp, csr, t16b, b2, h, N);                  // 9
    gemm_tc_kernel<64, false><<<gb, 256>>>(h, wf + 6144, t32, N);            // 10
    gather_f32_sig_kernel<<<wb, 256>>>(rp, csr, t32, b3, out, N);            // 11
}